// round 2
// baseline (speedup 1.0000x reference)
#include <cuda_runtime.h>
#include <math.h>

#define S   2048
#define HID 4096
#define NH  32
#define HD  128

// Scratch (device globals: allocation-free per harness rules)
__device__ float g_Q[S * HID];                 // 32 MB
__device__ float g_K[S * HID];                 // 32 MB
__device__ float g_V[S * HID];                 // 32 MB
__device__ float g_O[S * HID];                 // 32 MB
__device__ float g_P[(long)NH * S * S];        // 512 MB attention probs

// ---------------------------------------------------------------------------
// NT SGEMM: C[M,N] = alpha * A[M,K] @ B[N,K]^T   (both K-contiguous, row-major)
// 128x128 tile, BK=8, 256 threads, 8x8 microtile, double-buffered smem
// (register prefetch of next K-slice overlapped with FFMA; one barrier/iter).
// CAUSAL=1: skip tiles strictly above the block diagonal.
// blockIdx.z batches (heads) via sAz/sBz/sCz element strides.
// ---------------------------------------------------------------------------
template <int CAUSAL>
__global__ void __launch_bounds__(256) sgemm_nt(
    const float* __restrict__ A, const float* __restrict__ B, float* __restrict__ C,
    int K, int lda, int ldb, int ldc,
    long sAz, long sBz, long sCz, float alpha)
{
    if (CAUSAL && blockIdx.x > blockIdx.y) return;
    A += (long)blockIdx.z * sAz;
    B += (long)blockIdx.z * sBz;
    C += (long)blockIdx.z * sCz;

    __shared__ float As[2][8][128];
    __shared__ float Bs[2][8][128];

    const int tid  = threadIdx.x;
    const int row0 = blockIdx.y * 128;
    const int col0 = blockIdx.x * 128;
    const int lr = tid >> 1;            // 0..127
    const int lq = (tid & 1) * 4;       // 0 or 4
    const int tm = (tid >> 4) << 3;     // 0..120 step 8
    const int tn = (tid & 15) << 3;

    const float* Aptr = A + (long)(row0 + lr) * lda + lq;
    const float* Bptr = B + (long)(col0 + lr) * ldb + lq;

    float acc[8][8];
#pragma unroll
    for (int i = 0; i < 8; i++)
#pragma unroll
        for (int j = 0; j < 8; j++) acc[i][j] = 0.0f;

    // prologue: stage K-slice 0 into buffer 0
    float4 av = *(const float4*)(Aptr);
    float4 bv = *(const float4*)(Bptr);
    As[0][lq + 0][lr] = av.x; As[0][lq + 1][lr] = av.y;
    As[0][lq + 2][lr] = av.z; As[0][lq + 3][lr] = av.w;
    Bs[0][lq + 0][lr] = bv.x; Bs[0][lq + 1][lr] = bv.y;
    Bs[0][lq + 2][lr] = bv.z; Bs[0][lq + 3][lr] = bv.w;
    __syncthreads();

    int p = 0;
    for (int k0 = 0; k0 < K; k0 += 8) {
        const bool has_next = (k0 + 8) < K;
        if (has_next) {
            av = *(const float4*)(Aptr + k0 + 8);
            bv = *(const float4*)(Bptr + k0 + 8);
        }
#pragma unroll
        for (int kk = 0; kk < 8; kk++) {
            float a[8], b[8];
#pragma unroll
            for (int i = 0; i < 8; i++) a[i] = As[p][kk][tm + i];
#pragma unroll
            for (int j = 0; j < 8; j++) b[j] = Bs[p][kk][tn + j];
#pragma unroll
            for (int i = 0; i < 8; i++)
#pragma unroll
                for (int j = 0; j < 8; j++) acc[i][j] += a[i] * b[j];
        }
        if (has_next) {
            int np = p ^ 1;
            As[np][lq + 0][lr] = av.x; As[np][lq + 1][lr] = av.y;
            As[np][lq + 2][lr] = av.z; As[np][lq + 3][lr] = av.w;
            Bs[np][lq + 0][lr] = bv.x; Bs[np][lq + 1][lr] = bv.y;
            Bs[np][lq + 2][lr] = bv.z; Bs[np][lq + 3][lr] = bv.w;
            __syncthreads();
            p = np;
        }
    }

#pragma unroll
    for (int i = 0; i < 8; i++) {
        float* cp = C + (long)(row0 + tm + i) * ldc + col0 + tn;
        float4 v0 = make_float4(alpha*acc[i][0], alpha*acc[i][1], alpha*acc[i][2], alpha*acc[i][3]);
        float4 v1 = make_float4(alpha*acc[i][4], alpha*acc[i][5], alpha*acc[i][6], alpha*acc[i][7]);
        *(float4*)(cp)     = v0;
        *(float4*)(cp + 4) = v1;
    }
}

// ---------------------------------------------------------------------------
// NN SGEMM: C[M,N] = A[M,K] @ B[K,N]  (A K-contiguous, B N-contiguous)
// Same tiling + double buffering.
// KLIMIT=1: bound the K loop at (blockIdx.y+1)*128 (causal P has zeros beyond).
// ---------------------------------------------------------------------------
template <int KLIMIT>
__global__ void __launch_bounds__(256) sgemm_nn(
    const float* __restrict__ A, const float* __restrict__ B, float* __restrict__ C,
    int K, int lda, int ldb, int ldc,
    long sAz, long sBz, long sCz)
{
    A += (long)blockIdx.z * sAz;
    B += (long)blockIdx.z * sBz;
    C += (long)blockIdx.z * sCz;

    __shared__ float As[2][8][128];
    __shared__ float Bs[2][8][128];

    const int tid  = threadIdx.x;
    const int row0 = blockIdx.y * 128;
    const int col0 = blockIdx.x * 128;
    const int lrA = tid >> 1, lqA = (tid & 1) * 4;
    const int lrB = tid >> 5, lcB = (tid & 31) * 4;
    const int tm = (tid >> 4) << 3;
    const int tn = (tid & 15) << 3;

    const float* Aptr = A + (long)(row0 + lrA) * lda + lqA;
    const float* Bptr = B + (long)lrB * ldb + col0 + lcB;

    int Keff = KLIMIT ? min(K, (int)(blockIdx.y + 1) * 128) : K;

    float acc[8][8];
#pragma unroll
    for (int i = 0; i < 8; i++)
#pragma unroll
        for (int j = 0; j < 8; j++) acc[i][j] = 0.0f;

    float4 av = *(const float4*)(Aptr);
    float4 bv = *(const float4*)(Bptr);
    As[0][lqA + 0][lrA] = av.x; As[0][lqA + 1][lrA] = av.y;
    As[0][lqA + 2][lrA] = av.z; As[0][lqA + 3][lrA] = av.w;
    *(float4*)&Bs[0][lrB][lcB] = bv;
    __syncthreads();

    int p = 0;
    for (int k0 = 0; k0 < Keff; k0 += 8) {
        const bool has_next = (k0 + 8) < Keff;
        if (has_next) {
            av = *(const float4*)(Aptr + k0 + 8);
            bv = *(const float4*)(Bptr + (long)(k0 + 8) * ldb);
        }
#pragma unroll
        for (int kk = 0; kk < 8; kk++) {
            float a[8], b[8];
#pragma unroll
            for (int i = 0; i < 8; i++) a[i] = As[p][kk][tm + i];
#pragma unroll
            for (int j = 0; j < 8; j++) b[j] = Bs[p][kk][tn + j];
#pragma unroll
            for (int i = 0; i < 8; i++)
#pragma unroll
                for (int j = 0; j < 8; j++) acc[i][j] += a[i] * b[j];
        }
        if (has_next) {
            int np = p ^ 1;
            As[np][lqA + 0][lrA] = av.x; As[np][lqA + 1][lrA] = av.y;
            As[np][lqA + 2][lrA] = av.z; As[np][lqA + 3][lrA] = av.w;
            *(float4*)&Bs[np][lrB][lcB] = bv;
            __syncthreads();
            p = np;
        }
    }

#pragma unroll
    for (int i = 0; i < 8; i++) {
        float* cp = C + (long)(row0 + tm + i) * ldc + col0 + tn;
        *(float4*)(cp)     = make_float4(acc[i][0], acc[i][1], acc[i][2], acc[i][3]);
        *(float4*)(cp + 4) = make_float4(acc[i][4], acc[i][5], acc[i][6], acc[i][7]);
    }
}

// ---------------------------------------------------------------------------
// RoPE applied in-place to Q and K. One thread per (s, h, d<64) pair.
// ---------------------------------------------------------------------------
__global__ void rope_kernel(const int* __restrict__ pos,
                            float* __restrict__ Q, float* __restrict__ Km)
{
    int idx = blockIdx.x * blockDim.x + threadIdx.x;   // S*NH*64 threads
    int d = idx & 63;
    int h = (idx >> 6) & (NH - 1);
    int s = idx >> 11;
    if (s >= S) return;

    float p = (float)pos[s];
    float invf = powf(10000.0f, -(float)(2 * d) / (float)HD);
    float ang = p * invf;
    float c = cosf(ang), sn = sinf(ang);

    long base = (long)s * HID + h * HD;
    float q1 = Q[base + d], q2 = Q[base + d + 64];
    Q[base + d]      = q1 * c - q2 * sn;
    Q[base + d + 64] = q2 * c + q1 * sn;
    float k1 = Km[base + d], k2 = Km[base + d + 64];
    Km[base + d]      = k1 * c - k2 * sn;
    Km[base + d + 64] = k2 * c + k1 * sn;
}

// ---------------------------------------------------------------------------
// Causal softmax over one row of g_P. Row kept in registers (8 per thread).
// Writes exact zeros for k > q so P is clean everywhere afterwards.
// ---------------------------------------------------------------------------
__global__ void __launch_bounds__(256) softmax_kernel(float* __restrict__ P)
{
    int q = blockIdx.x, h = blockIdx.y;
    float* row = P + ((long)h * S + q) * S;
    int len = q + 1;
    int tid = threadIdx.x;
    __shared__ float red[256];

    float v[8];
    float mx = -3.4e38f;
#pragma unroll
    for (int i = 0; i < 8; i++) {
        int k = tid + i * 256;
        v[i] = (k < len) ? row[k] : -3.4e38f;
        mx = fmaxf(mx, v[i]);
    }
    red[tid] = mx; __syncthreads();
    for (int st = 128; st > 0; st >>= 1) {
        if (tid < st) red[tid] = fmaxf(red[tid], red[tid + st]);
        __syncthreads();
    }
    mx = red[0]; __syncthreads();

    float sum = 0.0f;
#pragma unroll
    for (int i = 0; i < 8; i++) {
        int k = tid + i * 256;
        v[i] = (k < len) ? expf(v[i] - mx) : 0.0f;
        sum += v[i];
    }
    red[tid] = sum; __syncthreads();
    for (int st = 128; st > 0; st >>= 1) {
        if (tid < st) red[tid] += red[tid + st];
        __syncthreads();
    }
    float inv = 1.0f / red[0];
#pragma unroll
    for (int i = 0; i < 8; i++) {
        int k = tid + i * 256;
        row[k] = v[i] * inv;        // zeros for k > q
    }
}

// ---------------------------------------------------------------------------
// attention_dispense for (512,1024) [z=0] and (1024,1536) [z=1].
// The two dispenses modify disjoint rows -> single parallel launch.
// ---------------------------------------------------------------------------
__global__ void __launch_bounds__(256) dispense_kernel(float* __restrict__ P)
{
    const int which = blockIdx.z;
    const int start = which ? 1024 : 512;
    const int end   = start + 512;
    const int q = start + blockIdx.x;
    const int h = blockIdx.y;
    float* row = P + ((long)h * S + q) * S;
    const float lb = 0.5f / (float)end;
    const int tid = threadIdx.x;
    __shared__ float red[256];

    float v[6];
    float s_local = 0.0f;
#pragma unroll
    for (int i = 0; i < 6; i++) {
        int k = tid + i * 256;
        float x = (k < end) ? row[k] : 0.0f;
        x = (x >= lb) ? x : 0.0f;          // mask
        if (k == 0) x *= 0.5f;             // blk[...,0] /= 2
        v[i] = x;
        s_local += x;
    }
    red[tid] = s_local; __syncthreads();
    for (int st = 128; st > 0; st >>= 1) {
        if (tid < st) red[tid] += red[tid + st];
        __syncthreads();
    }
    float elim = 1.0f - red[0];
    __syncthreads();

    if (which == 1) {
        // prev = cols [0,1024) (masked+halved values), prev_mask = v>=lb ? 1 : 0.01
        float pm[6]; float nzl = 0.0f;
#pragma unroll
        for (int i = 0; i < 6; i++) {
            int k = tid + i * 256;
            if (k < 1024) { pm[i] = (v[i] >= lb) ? 1.0f : 0.01f; nzl += pm[i]; }
            else pm[i] = 0.0f;
        }
        red[tid] = nzl; __syncthreads();
        for (int st = 128; st > 0; st >>= 1) {
            if (tid < st) red[tid] += red[tid + st];
            __syncthreads();
        }
        float add = elim / red[0] * 0.1f;
#pragma unroll
        for (int i = 0; i < 6; i++) {
            int k = tid + i * 256;
            if (k < 512)       v[i] += 3.0f * add * pm[i];
            else if (k < 1024) v[i] += 7.0f * add * pm[i];
        }
    } else {
        // prev = cols [0,512), prev_mask = v>=lb ? 1 : 0.001, factor 10
        float pm[6]; float nzl = 0.0f;
#pragma unroll
        for (int i = 0; i < 6; i++) {
            int k = tid + i * 256;
            if (k < 512) { pm[i] = (v[i] >= lb) ? 1.0f : 0.001f; nzl += pm[i]; }
            else pm[i] = 0.0f;
        }
        red[tid] = nzl; __syncthreads();
        for (int st = 128; st > 0; st >>= 1) {
            if (tid < st) red[tid] += red[tid + st];
            __syncthreads();
        }
        float add = elim / red[0] * 0.1f;
#pragma unroll
        for (int i = 0; i < 6; i++) {
            int k = tid + i * 256;
            if (k < 512) v[i] += 10.0f * add * pm[i];
        }
    }

#pragma unroll
    for (int i = 0; i < 6; i++) {
        int k = tid + i * 256;
        if (k < end) row[k] = v[i];
    }
}

// ---------------------------------------------------------------------------
extern "C" void kernel_launch(void* const* d_in, const int* in_sizes, int n_in,
                              void* d_out, int out_size)
{
    (void)in_sizes; (void)n_in; (void)out_size;
    const float* hidden = (const float*)d_in[0];
    // d_in[1] = attention_mask: pure causal, handled analytically.
    const int*   pos    = (const int*)d_in[2];
    const float* wq     = (const float*)d_in[3];
    const float* wk     = (const float*)d_in[4];
    const float* wv     = (const float*)d_in[5];
    const float* wo     = (const float*)d_in[6];
    float* out = (float*)d_out;

    float *pQ, *pK, *pV, *pP, *pO;
    cudaGetSymbolAddress((void**)&pQ, g_Q);
    cudaGetSymbolAddress((void**)&pK, g_K);
    cudaGetSymbolAddress((void**)&pV, g_V);
    cudaGetSymbolAddress((void**)&pP, g_P);
    cudaGetSymbolAddress((void**)&pO, g_O);

    dim3 blk(256);
    const float scale = 0.08838834764831845f;   // 1/sqrt(128)

    // Q/K/V projections: [2048,4096] = hidden @ W^T
    dim3 gproj(HID / 128, S / 128, 1);
    sgemm_nt<0><<<gproj, blk>>>(hidden, wq, pQ, HID, HID, HID, HID, 0, 0, 0, 1.0f);
    sgemm_nt<0><<<gproj, blk>>>(hidden, wk, pK, HID, HID, HID, HID, 0, 0, 0, 1.0f);
    sgemm_nt<0><<<gproj, blk>>>(hidden, wv, pV, HID, HID, HID, HID, 0, 0, 0, 1.0f);

    // RoPE in-place on Q, K
    rope_kernel<<<(S * NH * 64) / 256, 256>>>(pos, pQ, pK);

    // Scores: P_h = scale * Q_h @ K_h^T  (causal tile-skip)
    dim3 gscore(S / 128, S / 128, NH);
    sgemm_nt<1><<<gscore, blk>>>(pQ, pK, pP, HD, HID, HID, S,
                                 (long)HD, (long)HD, (long)S * S, scale);

    // Row softmax (causal, zero-fills above diagonal)
    softmax_kernel<<<dim3(S, NH), 256>>>(pP);

    // attention_dispense for both (start,end) blocks (disjoint rows)
    dispense_kernel<<<dim3(512, NH, 2), 256>>>(pP);

    // O_h = P_h @ V_h  (K loop bounded by causal structure)
    dim3 gpv(1, S / 128, NH);
    sgemm_nn<1><<<gpv, blk>>>(pP, pV, pO, S, S, HID, HID,
                              (long)S * S, (long)HD, (long)HD);

    // Final: out = O @ wo^T
    sgemm_nt<0><<<gproj, blk>>>(pO, wo, out, HID, HID, HID, HID, 0, 0, 0, 1.0f);
}

// round 3
// speedup vs baseline: 1.3989x; 1.3989x over previous
#include <cuda_runtime.h>
#include <math.h>

#define S   2048
#define HID 4096
#define NH  32
#define HD  128

// Scratch (device globals: allocation-free per harness rules)
__device__ float g_Q[S * HID];                 // 32 MB
__device__ float g_K[S * HID];                 // 32 MB
__device__ float g_V[S * HID];                 // 32 MB
__device__ float g_O[S * HID];                 // 32 MB
__device__ float g_P[(long)NH * S * S];        // 512 MB attention probs

// ---------------------------------------------------------------------------
// 3xTF32 helpers
// ---------------------------------------------------------------------------
__device__ __forceinline__ void cvt_split(float v, float& hi, float& lo)
{
    unsigned h;
    asm("cvt.rna.tf32.f32 %0, %1;" : "=r"(h) : "f"(v));
    hi = __uint_as_float(h);
    float r = v - hi;
    unsigned l;
    asm("cvt.rna.tf32.f32 %0, %1;" : "=r"(l) : "f"(r));
    lo = __uint_as_float(l);
}

__device__ __forceinline__ void mma_tf32(float4& c,
    unsigned a0, unsigned a1, unsigned a2, unsigned a3,
    unsigned b0, unsigned b1)
{
    asm("mma.sync.aligned.m16n8k8.row.col.f32.tf32.tf32.f32 "
        "{%0,%1,%2,%3},{%4,%5,%6,%7},{%8,%9},{%0,%1,%2,%3};"
        : "+f"(c.x), "+f"(c.y), "+f"(c.z), "+f"(c.w)
        : "r"(a0), "r"(a1), "r"(a2), "r"(a3), "r"(b0), "r"(b1));
}

#define SMW 136   // smem row stride: 136 % 32 == 8 -> conflict-free frag loads

// ---------------------------------------------------------------------------
// NT tensor GEMM: C[M,N] = alpha * A[M,K] @ B[N,K]^T  (both K-contiguous)
// 128x128 tile, BK=8, 256 thr, warp tile 64x32, 3xTF32, double buffered.
// CAUSAL=1: skip tiles strictly above the block diagonal.
// ---------------------------------------------------------------------------
template <int CAUSAL>
__global__ void __launch_bounds__(256) tgemm_nt(
    const float* __restrict__ A, const float* __restrict__ B, float* __restrict__ C,
    int K, int lda, int ldb, int ldc,
    long sAz, long sBz, long sCz, float alpha)
{
    if (CAUSAL && blockIdx.x > blockIdx.y) return;
    A += (long)blockIdx.z * sAz;
    B += (long)blockIdx.z * sBz;
    C += (long)blockIdx.z * sCz;

    __shared__ float Ah[2][8][SMW], Al[2][8][SMW];
    __shared__ float Bh[2][8][SMW], Bl[2][8][SMW];

    const int tid  = threadIdx.x;
    const int warp = tid >> 5, lane = tid & 31;
    const int wm = warp & 1, wn = warp >> 1;      // 2x4 warp grid
    const int gid = lane >> 2, tig = lane & 3;
    const int row0 = blockIdx.y * 128;
    const int col0 = blockIdx.x * 128;
    const int lr = tid >> 1;                       // 0..127
    const int lq = (tid & 1) * 4;                  // 0 or 4

    const float* Aptr = A + (long)(row0 + lr) * lda + lq;
    const float* Bptr = B + (long)(col0 + lr) * ldb + lq;

    float4 acc[4][4];
#pragma unroll
    for (int i = 0; i < 4; i++)
#pragma unroll
        for (int j = 0; j < 4; j++) acc[i][j] = make_float4(0.f, 0.f, 0.f, 0.f);

    // prologue
    float4 av = *(const float4*)(Aptr);
    float4 bv = *(const float4*)(Bptr);
    {
        float h, l;
        cvt_split(av.x, h, l); Ah[0][lq+0][lr] = h; Al[0][lq+0][lr] = l;
        cvt_split(av.y, h, l); Ah[0][lq+1][lr] = h; Al[0][lq+1][lr] = l;
        cvt_split(av.z, h, l); Ah[0][lq+2][lr] = h; Al[0][lq+2][lr] = l;
        cvt_split(av.w, h, l); Ah[0][lq+3][lr] = h; Al[0][lq+3][lr] = l;
        cvt_split(bv.x, h, l); Bh[0][lq+0][lr] = h; Bl[0][lq+0][lr] = l;
        cvt_split(bv.y, h, l); Bh[0][lq+1][lr] = h; Bl[0][lq+1][lr] = l;
        cvt_split(bv.z, h, l); Bh[0][lq+2][lr] = h; Bl[0][lq+2][lr] = l;
        cvt_split(bv.w, h, l); Bh[0][lq+3][lr] = h; Bl[0][lq+3][lr] = l;
    }
    __syncthreads();

    int p = 0;
    for (int k0 = 0; k0 < K; k0 += 8) {
        const bool has_next = (k0 + 8) < K;
        if (has_next) {
            av = *(const float4*)(Aptr + k0 + 8);
            bv = *(const float4*)(Bptr + k0 + 8);
        }

        unsigned ah[4][4], al4[4][4];
#pragma unroll
        for (int mi = 0; mi < 4; mi++) {
            int m0 = wm * 64 + mi * 16 + gid;
            ah[mi][0]  = __float_as_uint(Ah[p][tig  ][m0]);
            ah[mi][1]  = __float_as_uint(Ah[p][tig  ][m0 + 8]);
            ah[mi][2]  = __float_as_uint(Ah[p][tig+4][m0]);
            ah[mi][3]  = __float_as_uint(Ah[p][tig+4][m0 + 8]);
            al4[mi][0] = __float_as_uint(Al[p][tig  ][m0]);
            al4[mi][1] = __float_as_uint(Al[p][tig  ][m0 + 8]);
            al4[mi][2] = __float_as_uint(Al[p][tig+4][m0]);
            al4[mi][3] = __float_as_uint(Al[p][tig+4][m0 + 8]);
        }
#pragma unroll
        for (int ni = 0; ni < 4; ni++) {
            int n0 = wn * 32 + ni * 8 + gid;
            unsigned bh0 = __float_as_uint(Bh[p][tig  ][n0]);
            unsigned bh1 = __float_as_uint(Bh[p][tig+4][n0]);
            unsigned bl0 = __float_as_uint(Bl[p][tig  ][n0]);
            unsigned bl1 = __float_as_uint(Bl[p][tig+4][n0]);
#pragma unroll
            for (int mi = 0; mi < 4; mi++) {
                mma_tf32(acc[mi][ni], ah[mi][0], ah[mi][1], ah[mi][2], ah[mi][3], bh0, bh1);
                mma_tf32(acc[mi][ni], ah[mi][0], ah[mi][1], ah[mi][2], ah[mi][3], bl0, bl1);
                mma_tf32(acc[mi][ni], al4[mi][0], al4[mi][1], al4[mi][2], al4[mi][3], bh0, bh1);
            }
        }

        if (has_next) {
            int np = p ^ 1;
            float h, l;
            cvt_split(av.x, h, l); Ah[np][lq+0][lr] = h; Al[np][lq+0][lr] = l;
            cvt_split(av.y, h, l); Ah[np][lq+1][lr] = h; Al[np][lq+1][lr] = l;
            cvt_split(av.z, h, l); Ah[np][lq+2][lr] = h; Al[np][lq+2][lr] = l;
            cvt_split(av.w, h, l); Ah[np][lq+3][lr] = h; Al[np][lq+3][lr] = l;
            cvt_split(bv.x, h, l); Bh[np][lq+0][lr] = h; Bl[np][lq+0][lr] = l;
            cvt_split(bv.y, h, l); Bh[np][lq+1][lr] = h; Bl[np][lq+1][lr] = l;
            cvt_split(bv.z, h, l); Bh[np][lq+2][lr] = h; Bl[np][lq+2][lr] = l;
            cvt_split(bv.w, h, l); Bh[np][lq+3][lr] = h; Bl[np][lq+3][lr] = l;
            __syncthreads();
            p = np;
        }
    }

#pragma unroll
    for (int mi = 0; mi < 4; mi++) {
        int r0 = row0 + wm * 64 + mi * 16 + gid;
        int r1 = r0 + 8;
#pragma unroll
        for (int ni = 0; ni < 4; ni++) {
            int c = col0 + wn * 32 + ni * 8 + 2 * tig;
            float2 v0 = make_float2(alpha * acc[mi][ni].x, alpha * acc[mi][ni].y);
            float2 v1 = make_float2(alpha * acc[mi][ni].z, alpha * acc[mi][ni].w);
            *(float2*)(C + (long)r0 * ldc + c) = v0;
            *(float2*)(C + (long)r1 * ldc + c) = v1;
        }
    }
}

// ---------------------------------------------------------------------------
// NN tensor GEMM: C[M,N] = A[M,K] @ B[K,N]  (A K-contig, B N-contig), 3xTF32.
// KLIMIT=1: bound K loop at (blockIdx.y+1)*128 (causal P zeros beyond).
// ---------------------------------------------------------------------------
template <int KLIMIT>
__global__ void __launch_bounds__(256) tgemm_nn(
    const float* __restrict__ A, const float* __restrict__ B, float* __restrict__ C,
    int K, int lda, int ldb, int ldc,
    long sAz, long sBz, long sCz)
{
    A += (long)blockIdx.z * sAz;
    B += (long)blockIdx.z * sBz;
    C += (long)blockIdx.z * sCz;

    __shared__ float Ah[2][8][SMW], Al[2][8][SMW];
    __shared__ float Bh[2][8][SMW], Bl[2][8][SMW];

    const int tid  = threadIdx.x;
    const int warp = tid >> 5, lane = tid & 31;
    const int wm = warp & 1, wn = warp >> 1;
    const int gid = lane >> 2, tig = lane & 3;
    const int row0 = blockIdx.y * 128;
    const int col0 = blockIdx.x * 128;
    const int lrA = tid >> 1, lqA = (tid & 1) * 4;
    const int lrB = tid >> 5, lcB = (tid & 31) * 4;

    const float* Aptr = A + (long)(row0 + lrA) * lda + lqA;
    const float* Bptr = B + (long)lrB * ldb + col0 + lcB;

    int Keff = KLIMIT ? min(K, (int)(blockIdx.y + 1) * 128) : K;

    float4 acc[4][4];
#pragma unroll
    for (int i = 0; i < 4; i++)
#pragma unroll
        for (int j = 0; j < 4; j++) acc[i][j] = make_float4(0.f, 0.f, 0.f, 0.f);

    float4 av = *(const float4*)(Aptr);
    float4 bv = *(const float4*)(Bptr);
    {
        float h, l;
        cvt_split(av.x, h, l); Ah[0][lqA+0][lrA] = h; Al[0][lqA+0][lrA] = l;
        cvt_split(av.y, h, l); Ah[0][lqA+1][lrA] = h; Al[0][lqA+1][lrA] = l;
        cvt_split(av.z, h, l); Ah[0][lqA+2][lrA] = h; Al[0][lqA+2][lrA] = l;
        cvt_split(av.w, h, l); Ah[0][lqA+3][lrA] = h; Al[0][lqA+3][lrA] = l;
        float4 bh4, bl4;
        cvt_split(bv.x, bh4.x, bl4.x); cvt_split(bv.y, bh4.y, bl4.y);
        cvt_split(bv.z, bh4.z, bl4.z); cvt_split(bv.w, bh4.w, bl4.w);
        *(float4*)&Bh[0][lrB][lcB] = bh4;
        *(float4*)&Bl[0][lrB][lcB] = bl4;
    }
    __syncthreads();

    int p = 0;
    for (int k0 = 0; k0 < Keff; k0 += 8) {
        const bool has_next = (k0 + 8) < Keff;
        if (has_next) {
            av = *(const float4*)(Aptr + k0 + 8);
            bv = *(const float4*)(Bptr + (long)(k0 + 8) * ldb);
        }

        unsigned ah[4][4], al4[4][4];
#pragma unroll
        for (int mi = 0; mi < 4; mi++) {
            int m0 = wm * 64 + mi * 16 + gid;
            ah[mi][0]  = __float_as_uint(Ah[p][tig  ][m0]);
            ah[mi][1]  = __float_as_uint(Ah[p][tig  ][m0 + 8]);
            ah[mi][2]  = __float_as_uint(Ah[p][tig+4][m0]);
            ah[mi][3]  = __float_as_uint(Ah[p][tig+4][m0 + 8]);
            al4[mi][0] = __float_as_uint(Al[p][tig  ][m0]);
            al4[mi][1] = __float_as_uint(Al[p][tig  ][m0 + 8]);
            al4[mi][2] = __float_as_uint(Al[p][tig+4][m0]);
            al4[mi][3] = __float_as_uint(Al[p][tig+4][m0 + 8]);
        }
#pragma unroll
        for (int ni = 0; ni < 4; ni++) {
            int n0 = wn * 32 + ni * 8 + gid;
            unsigned bh0 = __float_as_uint(Bh[p][tig  ][n0]);
            unsigned bh1 = __float_as_uint(Bh[p][tig+4][n0]);
            unsigned bl0 = __float_as_uint(Bl[p][tig  ][n0]);
            unsigned bl1 = __float_as_uint(Bl[p][tig+4][n0]);
#pragma unroll
            for (int mi = 0; mi < 4; mi++) {
                mma_tf32(acc[mi][ni], ah[mi][0], ah[mi][1], ah[mi][2], ah[mi][3], bh0, bh1);
                mma_tf32(acc[mi][ni], ah[mi][0], ah[mi][1], ah[mi][2], ah[mi][3], bl0, bl1);
                mma_tf32(acc[mi][ni], al4[mi][0], al4[mi][1], al4[mi][2], al4[mi][3], bh0, bh1);
            }
        }

        if (has_next) {
            int np = p ^ 1;
            float h, l;
            cvt_split(av.x, h, l); Ah[np][lqA+0][lrA] = h; Al[np][lqA+0][lrA] = l;
            cvt_split(av.y, h, l); Ah[np][lqA+1][lrA] = h; Al[np][lqA+1][lrA] = l;
            cvt_split(av.z, h, l); Ah[np][lqA+2][lrA] = h; Al[np][lqA+2][lrA] = l;
            cvt_split(av.w, h, l); Ah[np][lqA+3][lrA] = h; Al[np][lqA+3][lrA] = l;
            float4 bh4, bl4;
            cvt_split(bv.x, bh4.x, bl4.x); cvt_split(bv.y, bh4.y, bl4.y);
            cvt_split(bv.z, bh4.z, bl4.z); cvt_split(bv.w, bh4.w, bl4.w);
            *(float4*)&Bh[np][lrB][lcB] = bh4;
            *(float4*)&Bl[np][lrB][lcB] = bl4;
            __syncthreads();
            p = np;
        }
    }

#pragma unroll
    for (int mi = 0; mi < 4; mi++) {
        int r0 = row0 + wm * 64 + mi * 16 + gid;
        int r1 = r0 + 8;
#pragma unroll
        for (int ni = 0; ni < 4; ni++) {
            int c = col0 + wn * 32 + ni * 8 + 2 * tig;
            *(float2*)(C + (long)r0 * ldc + c) = make_float2(acc[mi][ni].x, acc[mi][ni].y);
            *(float2*)(C + (long)r1 * ldc + c) = make_float2(acc[mi][ni].z, acc[mi][ni].w);
        }
    }
}

// ---------------------------------------------------------------------------
// RoPE applied in-place to Q and K. One thread per (s, h, d<64) pair.
// ---------------------------------------------------------------------------
__global__ void rope_kernel(const int* __restrict__ pos,
                            float* __restrict__ Q, float* __restrict__ Km)
{
    int idx = blockIdx.x * blockDim.x + threadIdx.x;   // S*NH*64 threads
    int d = idx & 63;
    int h = (idx >> 6) & (NH - 1);
    int s = idx >> 11;
    if (s >= S) return;

    float p = (float)pos[s];
    float invf = powf(10000.0f, -(float)(2 * d) / (float)HD);
    float ang = p * invf;
    float c = cosf(ang), sn = sinf(ang);

    long base = (long)s * HID + h * HD;
    float q1 = Q[base + d], q2 = Q[base + d + 64];
    Q[base + d]      = q1 * c - q2 * sn;
    Q[base + d + 64] = q2 * c + q1 * sn;
    float k1 = Km[base + d], k2 = Km[base + d + 64];
    Km[base + d]      = k1 * c - k2 * sn;
    Km[base + d + 64] = k2 * c + k1 * sn;
}

// ---------------------------------------------------------------------------
// Causal softmax over one row of g_P. Writes exact zeros for k > q.
// ---------------------------------------------------------------------------
__global__ void __launch_bounds__(256) softmax_kernel(float* __restrict__ P)
{
    int q = blockIdx.x, h = blockIdx.y;
    float* row = P + ((long)h * S + q) * S;
    int len = q + 1;
    int tid = threadIdx.x;
    __shared__ float red[256];

    float v[8];
    float mx = -3.4e38f;
#pragma unroll
    for (int i = 0; i < 8; i++) {
        int k = tid + i * 256;
        v[i] = (k < len) ? row[k] : -3.4e38f;
        mx = fmaxf(mx, v[i]);
    }
    red[tid] = mx; __syncthreads();
    for (int st = 128; st > 0; st >>= 1) {
        if (tid < st) red[tid] = fmaxf(red[tid], red[tid + st]);
        __syncthreads();
    }
    mx = red[0]; __syncthreads();

    float sum = 0.0f;
#pragma unroll
    for (int i = 0; i < 8; i++) {
        int k = tid + i * 256;
        v[i] = (k < len) ? expf(v[i] - mx) : 0.0f;
        sum += v[i];
    }
    red[tid] = sum; __syncthreads();
    for (int st = 128; st > 0; st >>= 1) {
        if (tid < st) red[tid] += red[tid + st];
        __syncthreads();
    }
    float inv = 1.0f / red[0];
#pragma unroll
    for (int i = 0; i < 8; i++) {
        int k = tid + i * 256;
        row[k] = v[i] * inv;        // zeros for k > q
    }
}

// ---------------------------------------------------------------------------
// attention_dispense for (512,1024) [z=0] and (1024,1536) [z=1].
// ---------------------------------------------------------------------------
__global__ void __launch_bounds__(256) dispense_kernel(float* __restrict__ P)
{
    const int which = blockIdx.z;
    const int start = which ? 1024 : 512;
    const int end   = start + 512;
    const int q = start + blockIdx.x;
    const int h = blockIdx.y;
    float* row = P + ((long)h * S + q) * S;
    const float lb = 0.5f / (float)end;
    const int tid = threadIdx.x;
    __shared__ float red[256];

    float v[6];
    float s_local = 0.0f;
#pragma unroll
    for (int i = 0; i < 6; i++) {
        int k = tid + i * 256;
        float x = (k < end) ? row[k] : 0.0f;
        x = (x >= lb) ? x : 0.0f;          // mask
        if (k == 0) x *= 0.5f;             // blk[...,0] /= 2
        v[i] = x;
        s_local += x;
    }
    red[tid] = s_local; __syncthreads();
    for (int st = 128; st > 0; st >>= 1) {
        if (tid < st) red[tid] += red[tid + st];
        __syncthreads();
    }
    float elim = 1.0f - red[0];
    __syncthreads();

    if (which == 1) {
        float pm[6]; float nzl = 0.0f;
#pragma unroll
        for (int i = 0; i < 6; i++) {
            int k = tid + i * 256;
            if (k < 1024) { pm[i] = (v[i] >= lb) ? 1.0f : 0.01f; nzl += pm[i]; }
            else pm[i] = 0.0f;
        }
        red[tid] = nzl; __syncthreads();
        for (int st = 128; st > 0; st >>= 1) {
            if (tid < st) red[tid] += red[tid + st];
            __syncthreads();
        }
        float add = elim / red[0] * 0.1f;
#pragma unroll
        for (int i = 0; i < 6; i++) {
            int k = tid + i * 256;
            if (k < 512)       v[i] += 3.0f * add * pm[i];
            else if (k < 1024) v[i] += 7.0f * add * pm[i];
        }
    } else {
        float pm[6]; float nzl = 0.0f;
#pragma unroll
        for (int i = 0; i < 6; i++) {
            int k = tid + i * 256;
            if (k < 512) { pm[i] = (v[i] >= lb) ? 1.0f : 0.001f; nzl += pm[i]; }
            else pm[i] = 0.0f;
        }
        red[tid] = nzl; __syncthreads();
        for (int st = 128; st > 0; st >>= 1) {
            if (tid < st) red[tid] += red[tid + st];
            __syncthreads();
        }
        float add = elim / red[0] * 0.1f;
#pragma unroll
        for (int i = 0; i < 6; i++) {
            int k = tid + i * 256;
            if (k < 512) v[i] += 10.0f * add * pm[i];
        }
    }

#pragma unroll
    for (int i = 0; i < 6; i++) {
        int k = tid + i * 256;
        if (k < end) row[k] = v[i];
    }
}

// ---------------------------------------------------------------------------
extern "C" void kernel_launch(void* const* d_in, const int* in_sizes, int n_in,
                              void* d_out, int out_size)
{
    (void)in_sizes; (void)n_in; (void)out_size;
    const float* hidden = (const float*)d_in[0];
    // d_in[1] = attention_mask: pure causal, handled analytically.
    const int*   pos    = (const int*)d_in[2];
    const float* wq     = (const float*)d_in[3];
    const float* wk     = (const float*)d_in[4];
    const float* wv     = (const float*)d_in[5];
    const float* wo     = (const float*)d_in[6];
    float* out = (float*)d_out;

    float *pQ, *pK, *pV, *pP, *pO;
    cudaGetSymbolAddress((void**)&pQ, g_Q);
    cudaGetSymbolAddress((void**)&pK, g_K);
    cudaGetSymbolAddress((void**)&pV, g_V);
    cudaGetSymbolAddress((void**)&pP, g_P);
    cudaGetSymbolAddress((void**)&pO, g_O);

    dim3 blk(256);
    const float scale = 0.08838834764831845f;   // 1/sqrt(128)

    // Q/K/V projections: [2048,4096] = hidden @ W^T
    dim3 gproj(HID / 128, S / 128, 1);
    tgemm_nt<0><<<gproj, blk>>>(hidden, wq, pQ, HID, HID, HID, HID, 0, 0, 0, 1.0f);
    tgemm_nt<0><<<gproj, blk>>>(hidden, wk, pK, HID, HID, HID, HID, 0, 0, 0, 1.0f);
    tgemm_nt<0><<<gproj, blk>>>(hidden, wv, pV, HID, HID, HID, HID, 0, 0, 0, 1.0f);

    // RoPE in-place on Q, K
    rope_kernel<<<(S * NH * 64) / 256, 256>>>(pos, pQ, pK);

    // Scores: P_h = scale * Q_h @ K_h^T  (causal tile-skip)
    dim3 gscore(S / 128, S / 128, NH);
    tgemm_nt<1><<<gscore, blk>>>(pQ, pK, pP, HD, HID, HID, S,
                                 (long)HD, (long)HD, (long)S * S, scale);

    // Row softmax (causal, zero-fills above diagonal)
    softmax_kernel<<<dim3(S, NH), 256>>>(pP);

    // attention_dispense for both (start,end) blocks (disjoint rows)
    dispense_kernel<<<dim3(512, NH, 2), 256>>>(pP);

    // O_h = P_h @ V_h  (K loop bounded by causal structure)
    dim3 gpv(1, S / 128, NH);
    tgemm_nn<1><<<gpv, blk>>>(pP, pV, pO, S, S, HID, HID,
                              (long)S * S, (long)HD, (long)HD);

    // Final: out = O @ wo^T
    tgemm_nt<0><<<gproj, blk>>>(pO, wo, out, HID, HID, HID, HID, 0, 0, 0, 1.0f);
}

// round 6
// speedup vs baseline: 1.7561x; 1.2554x over previous
#include <cuda_runtime.h>
#include <cuda_fp16.h>
#include <math.h>
#include <stdint.h>

#define S   2048
#define HID 4096
#define NH  32
#define HD  128

// Scratch (device globals: allocation-free per harness rules)
__device__ float g_Q[S * HID];
__device__ float g_K[S * HID];
__device__ float g_V[S * HID];
__device__ float g_O[S * HID];
__device__ float g_P[(long)NH * S * S];        // 512 MB attention probs

#define SMW2 136      // half2 words per kp-plane row: 136%32==8 -> conflict-free frags
#define LSCALE 1024.0f
#define INV_LSCALE (1.0f / 1024.0f)

// ---------------------------------------------------------------------------
// fp16 3-term split helpers. lo is scaled by 2^10 so weight residuals stay
// in fp16 normal range; the epilogue multiplies the cross accumulator by 2^-10.
// ---------------------------------------------------------------------------
struct HL4 { unsigned h0, h1, l0, l1; };   // (x,y) pair and (z,w) pair, hi & lo

__device__ __forceinline__ HL4 cvt4(float4 v)
{
    HL4 o;
    __half hx = __float2half_rn(v.x), hy = __float2half_rn(v.y);
    __half hz = __float2half_rn(v.z), hw = __float2half_rn(v.w);
    float rx = v.x - __half2float(hx), ry = v.y - __half2float(hy);
    float rz = v.z - __half2float(hz), rw = v.w - __half2float(hw);
    __half2 a = __halves2half2(hx, hy), b = __halves2half2(hz, hw);
    __half2 c = __floats2half2_rn(rx * LSCALE, ry * LSCALE);
    __half2 d = __floats2half2_rn(rz * LSCALE, rw * LSCALE);
    o.h0 = *(unsigned*)&a; o.h1 = *(unsigned*)&b;
    o.l0 = *(unsigned*)&c; o.l1 = *(unsigned*)&d;
    return o;
}
// pack two values from DIFFERENT source rows (k, k+1) into one half2 (NN B fill)
__device__ __forceinline__ void cvt_cross(float a, float b, unsigned& h, unsigned& l)
{
    __half ha = __float2half_rn(a), hb = __float2half_rn(b);
    float ra = a - __half2float(ha), rb = b - __half2float(hb);
    __half2 H = __halves2half2(ha, hb);
    __half2 L = __floats2half2_rn(ra * LSCALE, rb * LSCALE);
    h = *(unsigned*)&H; l = *(unsigned*)&L;
}

__device__ __forceinline__ void mma_f16(float4& c,
    unsigned a0, unsigned a1, unsigned a2, unsigned a3,
    unsigned b0, unsigned b1)
{
    asm("mma.sync.aligned.m16n8k16.row.col.f32.f16.f16.f32 "
        "{%0,%1,%2,%3},{%4,%5,%6,%7},{%8,%9},{%0,%1,%2,%3};"
        : "+f"(c.x), "+f"(c.y), "+f"(c.z), "+f"(c.w)
        : "r"(a0), "r"(a1), "r"(a2), "r"(a3), "r"(b0), "r"(b1));
}

// ---------------------------------------------------------------------------
// NT fp16-split GEMM: C[M,N] = alpha * A[M,K] @ B[N,K]^T (both K-contiguous)
// 128x128 tile, BK=16, 256 thr, warp tile 64x32, double-buffered.
// smem: [stage][kp(=k/2) 0..7][row 0..127] of half2 (uint), hi & lo planes.
// CAUSAL=1: skip tiles strictly above the block diagonal.
// ---------------------------------------------------------------------------
template <int CAUSAL>
__global__ void __launch_bounds__(256) hgemm_nt(
    const float* __restrict__ A, const float* __restrict__ B, float* __restrict__ C,
    int K, int lda, int ldb, int ldc,
    long sAz, long sBz, long sCz, float alpha)
{
    if (CAUSAL && blockIdx.x > blockIdx.y) return;
    A += (long)blockIdx.z * sAz;
    B += (long)blockIdx.z * sBz;
    C += (long)blockIdx.z * sCz;

    __shared__ unsigned Ah[2][8][SMW2], Al[2][8][SMW2];
    __shared__ unsigned Bh[2][8][SMW2], Bl[2][8][SMW2];

    const int tid  = threadIdx.x;
    const int warp = tid >> 5, lane = tid & 31;
    const int wm = warp & 1, wn = warp >> 1;          // 2x4 warp grid, tile 64x32
    const int gid = lane >> 2, tig = lane & 3;
    const int row0 = blockIdx.y * 128;
    const int col0 = blockIdx.x * 128;
    const int lr = tid >> 1;                           // 0..127
    const int kq = (tid & 1) * 8;                      // k offset 0 or 8
    const int kp0 = (tid & 1) * 4;                     // kp base 0 or 4

    const float* Aptr = A + (long)(row0 + lr) * lda + kq;
    const float* Bptr = B + (long)(col0 + lr) * ldb + kq;

    float4 acc[4][4], accx[4][4];
#pragma unroll
    for (int i = 0; i < 4; i++)
#pragma unroll
        for (int j = 0; j < 4; j++) {
            acc[i][j]  = make_float4(0.f, 0.f, 0.f, 0.f);
            accx[i][j] = make_float4(0.f, 0.f, 0.f, 0.f);
        }

    // prologue: stage 0
    {
        float4 a0 = *(const float4*)(Aptr);
        float4 a1 = *(const float4*)(Aptr + 4);
        float4 b0 = *(const float4*)(Bptr);
        float4 b1 = *(const float4*)(Bptr + 4);
        HL4 ca = cvt4(a0); HL4 cb = cvt4(a1);
        Ah[0][kp0+0][lr] = ca.h0; Ah[0][kp0+1][lr] = ca.h1;
        Ah[0][kp0+2][lr] = cb.h0; Ah[0][kp0+3][lr] = cb.h1;
        Al[0][kp0+0][lr] = ca.l0; Al[0][kp0+1][lr] = ca.l1;
        Al[0][kp0+2][lr] = cb.l0; Al[0][kp0+3][lr] = cb.l1;
        HL4 cc = cvt4(b0); HL4 cd = cvt4(b1);
        Bh[0][kp0+0][lr] = cc.h0; Bh[0][kp0+1][lr] = cc.h1;
        Bh[0][kp0+2][lr] = cd.h0; Bh[0][kp0+3][lr] = cd.h1;
        Bl[0][kp0+0][lr] = cc.l0; Bl[0][kp0+1][lr] = cc.l1;
        Bl[0][kp0+2][lr] = cd.l0; Bl[0][kp0+3][lr] = cd.l1;
    }
    __syncthreads();

    int p = 0;
    for (int k0 = 0; k0 < K; k0 += 16) {
        const bool has_next = (k0 + 16) < K;
        float4 a0, a1, b0, b1;
        if (has_next) {
            a0 = *(const float4*)(Aptr + k0 + 16);
            a1 = *(const float4*)(Aptr + k0 + 20);
            b0 = *(const float4*)(Bptr + k0 + 16);
            b1 = *(const float4*)(Bptr + k0 + 20);
        }

        unsigned ah[4][4], al[4][4];
#pragma unroll
        for (int mi = 0; mi < 4; mi++) {
            int m0 = wm * 64 + mi * 16 + gid;
            ah[mi][0] = Ah[p][tig  ][m0];  ah[mi][1] = Ah[p][tig  ][m0 + 8];
            ah[mi][2] = Ah[p][tig+4][m0];  ah[mi][3] = Ah[p][tig+4][m0 + 8];
            al[mi][0] = Al[p][tig  ][m0];  al[mi][1] = Al[p][tig  ][m0 + 8];
            al[mi][2] = Al[p][tig+4][m0];  al[mi][3] = Al[p][tig+4][m0 + 8];
        }
#pragma unroll
        for (int ni = 0; ni < 4; ni++) {
            int n0 = wn * 32 + ni * 8 + gid;
            unsigned bh0 = Bh[p][tig][n0], bh1 = Bh[p][tig+4][n0];
            unsigned bl0 = Bl[p][tig][n0], bl1 = Bl[p][tig+4][n0];
#pragma unroll
            for (int mi = 0; mi < 4; mi++) {
                mma_f16(acc[mi][ni],  ah[mi][0], ah[mi][1], ah[mi][2], ah[mi][3], bh0, bh1);
                mma_f16(accx[mi][ni], ah[mi][0], ah[mi][1], ah[mi][2], ah[mi][3], bl0, bl1);
                mma_f16(accx[mi][ni], al[mi][0], al[mi][1], al[mi][2], al[mi][3], bh0, bh1);
            }
        }

        if (has_next) {
            int np = p ^ 1;
            HL4 ca = cvt4(a0); HL4 cb = cvt4(a1);
            Ah[np][kp0+0][lr] = ca.h0; Ah[np][kp0+1][lr] = ca.h1;
            Ah[np][kp0+2][lr] = cb.h0; Ah[np][kp0+3][lr] = cb.h1;
            Al[np][kp0+0][lr] = ca.l0; Al[np][kp0+1][lr] = ca.l1;
            Al[np][kp0+2][lr] = cb.l0; Al[np][kp0+3][lr] = cb.l1;
            HL4 cc = cvt4(b0); HL4 cd = cvt4(b1);
            Bh[np][kp0+0][lr] = cc.h0; Bh[np][kp0+1][lr] = cc.h1;
            Bh[np][kp0+2][lr] = cd.h0; Bh[np][kp0+3][lr] = cd.h1;
            Bl[np][kp0+0][lr] = cc.l0; Bl[np][kp0+1][lr] = cc.l1;
            Bl[np][kp0+2][lr] = cd.l0; Bl[np][kp0+3][lr] = cd.l1;
            __syncthreads();
            p = np;
        }
    }

#pragma unroll
    for (int mi = 0; mi < 4; mi++) {
        int r0 = row0 + wm * 64 + mi * 16 + gid;
        int r1 = r0 + 8;
#pragma unroll
        for (int ni = 0; ni < 4; ni++) {
            int c = col0 + wn * 32 + ni * 8 + 2 * tig;
            float4 t = acc[mi][ni], x = accx[mi][ni];
            *(float2*)(C + (long)r0 * ldc + c) = make_float2(
                alpha * (t.x + x.x * INV_LSCALE), alpha * (t.y + x.y * INV_LSCALE));
            *(float2*)(C + (long)r1 * ldc + c) = make_float2(
                alpha * (t.z + x.z * INV_LSCALE), alpha * (t.w + x.w * INV_LSCALE));
        }
    }
}

// ---------------------------------------------------------------------------
// NN fp16-split GEMM: C[M,N] = A[M,K] @ B[K,N]  (A K-contig, B N-contig)
// KLIMIT=1: bound K loop at (blockIdx.y+1)*128 (causal P has zeros beyond).
// B fill packs k-row pairs into half2.
// ---------------------------------------------------------------------------
template <int KLIMIT>
__global__ void __launch_bounds__(256) hgemm_nn(
    const float* __restrict__ A, const float* __restrict__ B, float* __restrict__ C,
    int K, int lda, int ldb, int ldc,
    long sAz, long sBz, long sCz)
{
    A += (long)blockIdx.z * sAz;
    B += (long)blockIdx.z * sBz;
    C += (long)blockIdx.z * sCz;

    __shared__ unsigned Ah[2][8][SMW2], Al[2][8][SMW2];
    __shared__ unsigned Bh[2][8][SMW2], Bl[2][8][SMW2];

    const int tid  = threadIdx.x;
    const int warp = tid >> 5, lane = tid & 31;
    const int wm = warp & 1, wn = warp >> 1;
    const int gid = lane >> 2, tig = lane & 3;
    const int row0 = blockIdx.y * 128;
    const int col0 = blockIdx.x * 128;
    const int lr = tid >> 1;
    const int kq = (tid & 1) * 8;
    const int kp0 = (tid & 1) * 4;
    const int kpB = tid >> 5;                // 0..7: kp row pair for B fill
    const int ncB = (tid & 31) * 4;          // 4 cols per thread

    const float* Aptr = A + (long)(row0 + lr) * lda + kq;
    const float* Bptr = B + col0 + ncB;

    int Keff = KLIMIT ? min(K, (int)(blockIdx.y + 1) * 128) : K;

    float4 acc[4][4], accx[4][4];
#pragma unroll
    for (int i = 0; i < 4; i++)
#pragma unroll
        for (int j = 0; j < 4; j++) {
            acc[i][j]  = make_float4(0.f, 0.f, 0.f, 0.f);
            accx[i][j] = make_float4(0.f, 0.f, 0.f, 0.f);
        }

    // prologue: stage 0
    {
        float4 a0 = *(const float4*)(Aptr);
        float4 a1 = *(const float4*)(Aptr + 4);
        float4 b0 = *(const float4*)(Bptr + (long)(2 * kpB) * ldb);
        float4 b1 = *(const float4*)(Bptr + (long)(2 * kpB + 1) * ldb);
        HL4 ca = cvt4(a0); HL4 cb = cvt4(a1);
        Ah[0][kp0+0][lr] = ca.h0; Ah[0][kp0+1][lr] = ca.h1;
        Ah[0][kp0+2][lr] = cb.h0; Ah[0][kp0+3][lr] = cb.h1;
        Al[0][kp0+0][lr] = ca.l0; Al[0][kp0+1][lr] = ca.l1;
        Al[0][kp0+2][lr] = cb.l0; Al[0][kp0+3][lr] = cb.l1;
        unsigned h, l;
        cvt_cross(b0.x, b1.x, h, l); Bh[0][kpB][ncB+0] = h; Bl[0][kpB][ncB+0] = l;
        cvt_cross(b0.y, b1.y, h, l); Bh[0][kpB][ncB+1] = h; Bl[0][kpB][ncB+1] = l;
        cvt_cross(b0.z, b1.z, h, l); Bh[0][kpB][ncB+2] = h; Bl[0][kpB][ncB+2] = l;
        cvt_cross(b0.w, b1.w, h, l); Bh[0][kpB][ncB+3] = h; Bl[0][kpB][ncB+3] = l;
    }
    __syncthreads();

    int p = 0;
    for (int k0 = 0; k0 < Keff; k0 += 16) {
        const bool has_next = (k0 + 16) < Keff;
        float4 a0, a1, b0, b1;
        if (has_next) {
            a0 = *(const float4*)(Aptr + k0 + 16);
            a1 = *(const float4*)(Aptr + k0 + 20);
            b0 = *(const float4*)(Bptr + (long)(k0 + 16 + 2 * kpB) * ldb);
            b1 = *(const float4*)(Bptr + (long)(k0 + 16 + 2 * kpB + 1) * ldb);
        }

        unsigned ah[4][4], al[4][4];
#pragma unroll
        for (int mi = 0; mi < 4; mi++) {
            int m0 = wm * 64 + mi * 16 + gid;
            ah[mi][0] = Ah[p][tig  ][m0];  ah[mi][1] = Ah[p][tig  ][m0 + 8];
            ah[mi][2] = Ah[p][tig+4][m0];  ah[mi][3] = Ah[p][tig+4][m0 + 8];
            al[mi][0] = Al[p][tig  ][m0];  al[mi][1] = Al[p][tig  ][m0 + 8];
            al[mi][2] = Al[p][tig+4][m0];  al[mi][3] = Al[p][tig+4][m0 + 8];
        }
#pragma unroll
        for (int ni = 0; ni < 4; ni++) {
            int n0 = wn * 32 + ni * 8 + gid;
            unsigned bh0 = Bh[p][tig][n0], bh1 = Bh[p][tig+4][n0];
            unsigned bl0 = Bl[p][tig][n0], bl1 = Bl[p][tig+4][n0];
#pragma unroll
            for (int mi = 0; mi < 4; mi++) {
                mma_f16(acc[mi][ni],  ah[mi][0], ah[mi][1], ah[mi][2], ah[mi][3], bh0, bh1);
                mma_f16(accx[mi][ni], ah[mi][0], ah[mi][1], ah[mi][2], ah[mi][3], bl0, bl1);
                mma_f16(accx[mi][ni], al[mi][0], al[mi][1], al[mi][2], al[mi][3], bh0, bh1);
            }
        }

        if (has_next) {
            int np = p ^ 1;
            HL4 ca = cvt4(a0); HL4 cb = cvt4(a1);
            Ah[np][kp0+0][lr] = ca.h0; Ah[np][kp0+1][lr] = ca.h1;
            Ah[np][kp0+2][lr] = cb.h0; Ah[np][kp0+3][lr] = cb.h1;
            Al[np][kp0+0][lr] = ca.l0; Al[np][kp0+1][lr] = ca.l1;
            Al[np][kp0+2][lr] = cb.l0; Al[np][kp0+3][lr] = cb.l1;
            unsigned h, l;
            cvt_cross(b0.x, b1.x, h, l); Bh[np][kpB][ncB+0] = h; Bl[np][kpB][ncB+0] = l;
            cvt_cross(b0.y, b1.y, h, l); Bh[np][kpB][ncB+1] = h; Bl[np][kpB][ncB+1] = l;
            cvt_cross(b0.z, b1.z, h, l); Bh[np][kpB][ncB+2] = h; Bl[np][kpB][ncB+2] = l;
            cvt_cross(b0.w, b1.w, h, l); Bh[np][kpB][ncB+3] = h; Bl[np][kpB][ncB+3] = l;
            __syncthreads();
            p = np;
        }
    }

#pragma unroll
    for (int mi = 0; mi < 4; mi++) {
        int r0 = row0 + wm * 64 + mi * 16 + gid;
        int r1 = r0 + 8;
#pragma unroll
        for (int ni = 0; ni < 4; ni++) {
            int c = col0 + wn * 32 + ni * 8 + 2 * tig;
            float4 t = acc[mi][ni], x = accx[mi][ni];
            *(float2*)(C + (long)r0 * ldc + c) = make_float2(
                t.x + x.x * INV_LSCALE, t.y + x.y * INV_LSCALE);
            *(float2*)(C + (long)r1 * ldc + c) = make_float2(
                t.z + x.z * INV_LSCALE, t.w + x.w * INV_LSCALE);
        }
    }
}

// ---------------------------------------------------------------------------
// RoPE applied in-place to Q and K.
// ---------------------------------------------------------------------------
__global__ void rope_kernel(const int* __restrict__ pos,
                            float* __restrict__ Q, float* __restrict__ Km)
{
    int idx = blockIdx.x * blockDim.x + threadIdx.x;
    int d = idx & 63;
    int h = (idx >> 6) & (NH - 1);
    int s = idx >> 11;
    if (s >= S) return;

    float p = (float)pos[s];
    float invf = powf(10000.0f, -(float)(2 * d) / (float)HD);
    float ang = p * invf;
    float c = cosf(ang), sn = sinf(ang);

    long base = (long)s * HID + h * HD;
    float q1 = Q[base + d], q2 = Q[base + d + 64];
    Q[base + d]      = q1 * c - q2 * sn;
    Q[base + d + 64] = q2 * c + q1 * sn;
    float k1 = Km[base + d], k2 = Km[base + d + 64];
    Km[base + d]      = k1 * c - k2 * sn;
    Km[base + d + 64] = k2 * c + k1 * sn;
}

// ---------------------------------------------------------------------------
// Causal softmax (writes exact zeros above the diagonal).
// ---------------------------------------------------------------------------
__global__ void __launch_bounds__(256) softmax_kernel(float* __restrict__ P)
{
    int q = blockIdx.x, h = blockIdx.y;
    float* row = P + ((long)h * S + q) * S;
    int len = q + 1;
    int tid = threadIdx.x;
    __shared__ float red[256];

    float v[8];
    float mx = -3.4e38f;
#pragma unroll
    for (int i = 0; i < 8; i++) {
        int k = tid + i * 256;
        v[i] = (k < len) ? row[k] : -3.4e38f;
        mx = fmaxf(mx, v[i]);
    }
    red[tid] = mx; __syncthreads();
    for (int st = 128; st > 0; st >>= 1) {
        if (tid < st) red[tid] = fmaxf(red[tid], red[tid + st]);
        __syncthreads();
    }
    mx = red[0]; __syncthreads();

    float sum = 0.0f;
#pragma unroll
    for (int i = 0; i < 8; i++) {
        int k = tid + i * 256;
        v[i] = (k < len) ? expf(v[i] - mx) : 0.0f;
        sum += v[i];
    }
    red[tid] = sum; __syncthreads();
    for (int st = 128; st > 0; st >>= 1) {
        if (tid < st) red[tid] += red[tid + st];
        __syncthreads();
    }
    float inv = 1.0f / red[0];
#pragma unroll
    for (int i = 0; i < 8; i++) {
        int k = tid + i * 256;
        row[k] = v[i] * inv;
    }
}

// ---------------------------------------------------------------------------
// attention_dispense for (512,1024) [z=0] and (1024,1536) [z=1].
// ---------------------------------------------------------------------------
__global__ void __launch_bounds__(256) dispense_kernel(float* __restrict__ P)
{
    const int which = blockIdx.z;
    const int start = which ? 1024 : 512;
    const int end   = start + 512;
    const int q = start + blockIdx.x;
    const int h = blockIdx.y;
    float* row = P + ((long)h * S + q) * S;
    const float lb = 0.5f / (float)end;
    const int tid = threadIdx.x;
    __shared__ float red[256];

    float v[6];
    float s_local = 0.0f;
#pragma unroll
    for (int i = 0; i < 6; i++) {
        int k = tid + i * 256;
        float x = (k < end) ? row[k] : 0.0f;
        x = (x >= lb) ? x : 0.0f;
        if (k == 0) x *= 0.5f;
        v[i] = x;
        s_local += x;
    }
    red[tid] = s_local; __syncthreads();
    for (int st = 128; st > 0; st >>= 1) {
        if (tid < st) red[tid] += red[tid + st];
        __syncthreads();
    }
    float elim = 1.0f - red[0];
    __syncthreads();

    if (which == 1) {
        float pm[6]; float nzl = 0.0f;
#pragma unroll
        for (int i = 0; i < 6; i++) {
            int k = tid + i * 256;
            if (k < 1024) { pm[i] = (v[i] >= lb) ? 1.0f : 0.01f; nzl += pm[i]; }
            else pm[i] = 0.0f;
        }
        red[tid] = nzl; __syncthreads();
        for (int st = 128; st > 0; st >>= 1) {
            if (tid < st) red[tid] += red[tid + st];
            __syncthreads();
        }
        float add = elim / red[0] * 0.1f;
#pragma unroll
        for (int i = 0; i < 6; i++) {
            int k = tid + i * 256;
            if (k < 512)       v[i] += 3.0f * add * pm[i];
            else if (k < 1024) v[i] += 7.0f * add * pm[i];
        }
    } else {
        float pm[6]; float nzl = 0.0f;
#pragma unroll
        for (int i = 0; i < 6; i++) {
            int k = tid + i * 256;
            if (k < 512) { pm[i] = (v[i] >= lb) ? 1.0f : 0.001f; nzl += pm[i]; }
            else pm[i] = 0.0f;
        }
        red[tid] = nzl; __syncthreads();
        for (int st = 128; st > 0; st >>= 1) {
            if (tid < st) red[tid] += red[tid + st];
            __syncthreads();
        }
        float add = elim / red[0] * 0.1f;
#pragma unroll
        for (int i = 0; i < 6; i++) {
            int k = tid + i * 256;
            if (k < 512) v[i] += 10.0f * add * pm[i];
        }
    }

#pragma unroll
    for (int i = 0; i < 6; i++) {
        int k = tid + i * 256;
        if (k < end) row[k] = v[i];
    }
}

// ---------------------------------------------------------------------------
extern "C" void kernel_launch(void* const* d_in, const int* in_sizes, int n_in,
                              void* d_out, int out_size)
{
    (void)in_sizes; (void)n_in; (void)out_size;
    const float* hidden = (const float*)d_in[0];
    const int*   pos    = (const int*)d_in[2];
    const float* wq     = (const float*)d_in[3];
    const float* wk     = (const float*)d_in[4];
    const float* wv     = (const float*)d_in[5];
    const float* wo     = (const float*)d_in[6];
    float* out = (float*)d_out;

    float *pQ, *pK, *pV, *pP, *pO;
    cudaGetSymbolAddress((void**)&pQ, g_Q);
    cudaGetSymbolAddress((void**)&pK, g_K);
    cudaGetSymbolAddress((void**)&pV, g_V);
    cudaGetSymbolAddress((void**)&pP, g_P);
    cudaGetSymbolAddress((void**)&pO, g_O);

    dim3 blk(256);
    const float scale = 0.08838834764831845f;   // 1/sqrt(128)

    // Q/K/V projections: [2048,4096] = hidden @ W^T
    dim3 gproj(HID / 128, S / 128, 1);
    hgemm_nt<0><<<gproj, blk>>>(hidden, wq, pQ, HID, HID, HID, HID, 0, 0, 0, 1.0f);
    hgemm_nt<0><<<gproj, blk>>>(hidden, wk, pK, HID, HID, HID, HID, 0, 0, 0, 1.0f);
    hgemm_nt<0><<<gproj, blk>>>(hidden, wv, pV, HID, HID, HID, HID, 0, 0, 0, 1.0f);

    // RoPE in-place on Q, K
    rope_kernel<<<(S * NH * 64) / 256, 256>>>(pos, pQ, pK);

    // Scores: P_h = scale * Q_h @ K_h^T  (causal tile-skip)
    dim3 gscore(S / 128, S / 128, NH);
    hgemm_nt<1><<<gscore, blk>>>(pQ, pK, pP, HD, HID, HID, S,
                                 (long)HD, (long)HD, (long)S * S, scale);

    softmax_kernel<<<dim3(S, NH), 256>>>(pP);
    dispense_kernel<<<dim3(512, NH, 2), 256>>>(pP);

    // O_h = P_h @ V_h  (K loop bounded by causal structure)
    dim3 gpv(1, S / 128, NH);
    hgemm_nn<1><<<gpv, blk>>>(pP, pV, pO, S, S, HID, HID,
                              (long)S * S, (long)HD, (long)HD);

    // Final: out = O @ wo^T
    hgemm_nt<0><<<gproj, blk>>>(pO, wo, out, HID, HID, HID, HID, 0, 0, 0, 1.0f);
}

// round 9
// speedup vs baseline: 1.8012x; 1.0257x over previous
#include <cuda_runtime.h>
#include <cuda_fp16.h>
#include <math.h>
#include <stdint.h>

#define S   2048
#define HID 4096
#define NH  32
#define HD  128

#define LSCALE 1024.0f
#define INV_LSCALE (1.0f / 1024.0f)

// ---------------------------------------------------------------------------
// Device scratch (allocation-free per harness rules)
// ---------------------------------------------------------------------------
__device__ float  g_Q[S * HID];
__device__ float  g_K[S * HID];
__device__ float  g_V[S * HID];
__device__ float  g_O[S * HID];
__device__ float  g_P[(long)NH * S * S];        // fp32 scores/probs (512 MB)

__device__ __half g_Hh[S * HID],  g_Hl[S * HID];          // hidden planes
__device__ __half g_Wqh[HID * HID], g_Wql[HID * HID];
__device__ __half g_Wkh[HID * HID], g_Wkl[HID * HID];
__device__ __half g_Wvh[HID * HID], g_Wvl[HID * HID];
__device__ __half g_Woh[HID * HID], g_Wol[HID * HID];
__device__ __half g_Qh[S * HID], g_Ql[S * HID];           // post-rope Q
__device__ __half g_Kh[S * HID], g_Kl[S * HID];           // post-rope K
__device__ __half g_Vth[NH * HD * S], g_Vtl[NH * HD * S]; // V transposed per head
__device__ __half g_Ph[(long)NH * S * S], g_Pl[(long)NH * S * S]; // P planes
__device__ __half g_Oh[S * HID], g_Ol[S * HID];           // attention out planes

// ---------------------------------------------------------------------------
// helpers
// ---------------------------------------------------------------------------
__device__ __forceinline__ void split_hl(float v, __half& h, __half& l)
{
    h = __float2half_rn(v);
    l = __float2half_rn((v - __half2float(h)) * LSCALE);
}

__device__ __forceinline__ uint32_t smem_u32(const void* p) {
    uint32_t a;
    asm("{ .reg .u64 t; cvta.to.shared.u64 t, %1; cvt.u32.u64 %0, t; }" : "=r"(a) : "l"(p));
    return a;
}
__device__ __forceinline__ void cp16(uint32_t dst, const void* src) {
    asm volatile("cp.async.ca.shared.global [%0], [%1], 16;" :: "r"(dst), "l"(src));
}
#define CP_COMMIT() asm volatile("cp.async.commit_group;" ::: "memory")
#define CP_WAIT1()  asm volatile("cp.async.wait_group 1;"  ::: "memory")
#define CP_WAIT0()  asm volatile("cp.async.wait_group 0;"  ::: "memory")

__device__ __forceinline__ void ldsm4(uint32_t& r0, uint32_t& r1, uint32_t& r2, uint32_t& r3, uint32_t a) {
    asm volatile("ldmatrix.sync.aligned.m8n8.x4.shared.b16 {%0,%1,%2,%3}, [%4];"
                 : "=r"(r0), "=r"(r1), "=r"(r2), "=r"(r3) : "r"(a));
}
__device__ __forceinline__ void ldsm2(uint32_t& r0, uint32_t& r1, uint32_t a) {
    asm volatile("ldmatrix.sync.aligned.m8n8.x2.shared.b16 {%0,%1}, [%2];"
                 : "=r"(r0), "=r"(r1) : "r"(a));
}
__device__ __forceinline__ void mma_f16(float4& c,
    uint32_t a0, uint32_t a1, uint32_t a2, uint32_t a3, uint32_t b0, uint32_t b1)
{
    asm("mma.sync.aligned.m16n8k16.row.col.f32.f16.f16.f32 "
        "{%0,%1,%2,%3},{%4,%5,%6,%7},{%8,%9},{%0,%1,%2,%3};"
        : "+f"(c.x), "+f"(c.y), "+f"(c.z), "+f"(c.w)
        : "r"(a0), "r"(a1), "r"(a2), "r"(a3), "r"(b0), "r"(b1));
}

// smem geometry: row stride 12 half2-words (48B) -> conflict-free ldmatrix
#define RSTR   12
#define PLANEB (128 * RSTR * 4)          // 6144 B per plane
#define STAGEB (4 * PLANEB)              // Ah, Al, Bh, Bl
#define SMEMB  (3 * STAGEB)              // 73728 B, 3-stage pipeline

// ---------------------------------------------------------------------------
// Pre-split NT GEMM: C[M,N] = alpha * (A) @ (B)^T, A/B given as half hi/lo
// planes, K-contiguous rows. 128x128 tile, BK=16, 256 thr, 3-stage cp.async,
// ldmatrix fragments, fp16 3-term split accumulation.
// CAUSAL: skip tiles above block diagonal. KLIMIT: Keff=(by+1)*128.
// ---------------------------------------------------------------------------
template <int CAUSAL, int KLIMIT>
__global__ void __launch_bounds__(256) hgemm_pre(
    const __half* __restrict__ Agh, const __half* __restrict__ Agl,
    const __half* __restrict__ Bgh, const __half* __restrict__ Bgl,
    float* __restrict__ C, int K, int lda, int ldb, int ldc,
    long sAz, long sBz, long sCz, float alpha)
{
    if (CAUSAL && blockIdx.x > blockIdx.y) return;
    extern __shared__ char sm[];

    const int row0 = blockIdx.y * 128;
    const int col0 = blockIdx.x * 128;
    Agh += (long)blockIdx.z * sAz + (long)row0 * lda;
    Agl += (long)blockIdx.z * sAz + (long)row0 * lda;
    Bgh += (long)blockIdx.z * sBz + (long)col0 * ldb;
    Bgl += (long)blockIdx.z * sBz + (long)col0 * ldb;
    C   += (long)blockIdx.z * sCz;

    const int tid = threadIdx.x;
    const int warp = tid >> 5, lane = tid & 31;
    const int wm = warp & 1, wn = warp >> 1;       // 2x4 warps, warp tile 64x32
    const int gid = lane >> 2, tig = lane & 3;

    const int Keff = KLIMIT ? min(K, (int)(blockIdx.y + 1) * 128) : K;
    const int NC = Keff >> 4;

    // fill indices: thread -> (row, 16B half of the 32B row chunk)
    const int frow = tid >> 1;
    const int fhf  = tid & 1;
    const uint32_t sb = smem_u32(sm);
    const uint32_t fdst = (uint32_t)(frow * RSTR + fhf * 4) * 4;
    const long fsA = (long)frow * lda + fhf * 8;
    const long fsB = (long)frow * ldb + fhf * 8;

    // ldmatrix lane offsets
    const int sub = lane >> 3;
    const int ar  = (lane & 7) + (sub & 1) * 8;
    const int ac  = (sub >> 1) * 4;                 // half2 words
    const int br  = lane & 7;
    const int bc  = ((lane >> 3) & 1) * 4;

    float4 acc[4][4], accx[4][4];
#pragma unroll
    for (int i = 0; i < 4; i++)
#pragma unroll
        for (int j = 0; j < 4; j++) {
            acc[i][j]  = make_float4(0.f, 0.f, 0.f, 0.f);
            accx[i][j] = make_float4(0.f, 0.f, 0.f, 0.f);
        }

    // prologue: stages 0 and 1
#pragma unroll
    for (int s = 0; s < 2; s++) {
        uint32_t d = sb + s * STAGEB + fdst;
        int k0 = s * 16;
        cp16(d,              Agh + fsA + k0);
        cp16(d + PLANEB,     Agl + fsA + k0);
        cp16(d + 2 * PLANEB, Bgh + fsB + k0);
        cp16(d + 3 * PLANEB, Bgl + fsB + k0);
        CP_COMMIT();
    }

    int stg = 0;
    for (int c = 0; c < NC; c++) {
        CP_WAIT1();
        __syncthreads();
        if (c + 2 < NC) {
            int ns = (stg + 2) % 3;
            uint32_t d = sb + ns * STAGEB + fdst;
            int k0 = (c + 2) * 16;
            cp16(d,              Agh + fsA + k0);
            cp16(d + PLANEB,     Agl + fsA + k0);
            cp16(d + 2 * PLANEB, Bgh + fsB + k0);
            cp16(d + 3 * PLANEB, Bgl + fsB + k0);
        }
        CP_COMMIT();   // empty group near tail keeps wait_group bookkeeping uniform

        const uint32_t s0 = sb + stg * STAGEB;
        uint32_t ah[4][4], al[4][4];
#pragma unroll
        for (int mi = 0; mi < 4; mi++) {
            uint32_t aoff = (uint32_t)((wm * 64 + mi * 16 + ar) * RSTR + ac) * 4;
            ldsm4(ah[mi][0], ah[mi][1], ah[mi][2], ah[mi][3], s0 + aoff);
            ldsm4(al[mi][0], al[mi][1], al[mi][2], al[mi][3], s0 + PLANEB + aoff);
        }
#pragma unroll
        for (int ni = 0; ni < 4; ni++) {
            uint32_t boff = (uint32_t)((wn * 32 + ni * 8 + br) * RSTR + bc) * 4;
            uint32_t bh0, bh1, bl0, bl1;
            ldsm2(bh0, bh1, s0 + 2 * PLANEB + boff);
            ldsm2(bl0, bl1, s0 + 3 * PLANEB + boff);
#pragma unroll
            for (int mi = 0; mi < 4; mi++) {
                mma_f16(acc[mi][ni],  ah[mi][0], ah[mi][1], ah[mi][2], ah[mi][3], bh0, bh1);
                mma_f16(accx[mi][ni], ah[mi][0], ah[mi][1], ah[mi][2], ah[mi][3], bl0, bl1);
                mma_f16(accx[mi][ni], al[mi][0], al[mi][1], al[mi][2], al[mi][3], bh0, bh1);
            }
        }
        stg = (stg + 1) % 3;
    }
    CP_WAIT0();

#pragma unroll
    for (int mi = 0; mi < 4; mi++) {
        int r0 = row0 + wm * 64 + mi * 16 + gid;
        int r1 = r0 + 8;
#pragma unroll
        for (int ni = 0; ni < 4; ni++) {
            int cc = col0 + wn * 32 + ni * 8 + 2 * tig;
            float4 t = acc[mi][ni], x = accx[mi][ni];
            *(float2*)(C + (long)r0 * ldc + cc) = make_float2(
                alpha * (t.x + x.x * INV_LSCALE), alpha * (t.y + x.y * INV_LSCALE));
            *(float2*)(C + (long)r1 * ldc + cc) = make_float2(
                alpha * (t.z + x.z * INV_LSCALE), alpha * (t.w + x.w * INV_LSCALE));
        }
    }
}

// ---------------------------------------------------------------------------
// Generic fp32 -> half hi/lo plane converter (float4 granularity).
// ---------------------------------------------------------------------------
__global__ void convert_kernel(const float* __restrict__ in,
                               __half* __restrict__ h, __half* __restrict__ l, long n4)
{
    long i = (long)blockIdx.x * blockDim.x + threadIdx.x;
    if (i >= n4) return;
    float4 v = ((const float4*)in)[i];
    __half hx, hy, hz, hw, lx, ly, lz, lw;
    split_hl(v.x, hx, lx); split_hl(v.y, hy, ly);
    split_hl(v.z, hz, lz); split_hl(v.w, hw, lw);
    __half2 h0 = __halves2half2(hx, hy), h1 = __halves2half2(hz, hw);
    __half2 l0 = __halves2half2(lx, ly), l1 = __halves2half2(lz, lw);
    ((__half2*)h)[2 * i] = h0; ((__half2*)h)[2 * i + 1] = h1;
    ((__half2*)l)[2 * i] = l0; ((__half2*)l)[2 * i + 1] = l1;
}

// ---------------------------------------------------------------------------
// RoPE: read fp32 Q/K, rotate, emit half hi/lo planes.
// ---------------------------------------------------------------------------
__global__ void rope_kernel(const int* __restrict__ pos,
                            const float* __restrict__ Q, const float* __restrict__ Km,
                            __half* __restrict__ Qh, __half* __restrict__ Ql,
                            __half* __restrict__ Kh, __half* __restrict__ Kl)
{
    int idx = blockIdx.x * blockDim.x + threadIdx.x;
    int d = idx & 63;
    int h = (idx >> 6) & (NH - 1);
    int s = idx >> 11;
    if (s >= S) return;

    float p = (float)pos[s];
    float invf = powf(10000.0f, -(float)(2 * d) / (float)HD);
    float ang = p * invf;
    float c = cosf(ang), sn = sinf(ang);

    long base = (long)s * HID + h * HD;
    float q1 = Q[base + d], q2 = Q[base + d + 64];
    float qa = q1 * c - q2 * sn;
    float qb = q2 * c + q1 * sn;
    float k1 = Km[base + d], k2 = Km[base + d + 64];
    float ka = k1 * c - k2 * sn;
    float kb = k2 * c + k1 * sn;

    __half hh, ll;
    split_hl(qa, hh, ll); Qh[base + d] = hh;      Ql[base + d] = ll;
    split_hl(qb, hh, ll); Qh[base + d + 64] = hh; Ql[base + d + 64] = ll;
    split_hl(ka, hh, ll); Kh[base + d] = hh;      Kl[base + d] = ll;
    split_hl(kb, hh, ll); Kh[base + d + 64] = hh; Kl[base + d + 64] = ll;
}

// ---------------------------------------------------------------------------
// Transpose-convert V: fp32 V[s][h*HD+n] -> half Vt[h][n][s] hi/lo.
// ---------------------------------------------------------------------------
__global__ void transpv_kernel(const float* __restrict__ V,
                               __half* __restrict__ Vth, __half* __restrict__ Vtl)
{
    __shared__ float t[32][33];
    int s0 = blockIdx.x * 32, n0 = blockIdx.y * 32, h = blockIdx.z;
    int tx = threadIdx.x, ty = threadIdx.y;
#pragma unroll
    for (int i = 0; i < 4; i++)
        t[ty + i * 8][tx] = V[(long)(s0 + ty + i * 8) * HID + h * HD + n0 + tx];
    __syncthreads();
#pragma unroll
    for (int i = 0; i < 4; i++) {
        float v = t[tx][ty + i * 8];
        __half hh, ll; split_hl(v, hh, ll);
        long o = ((long)h * HD + n0 + ty + i * 8) * S + s0 + tx;
        Vth[o] = hh; Vtl[o] = ll;
    }
}

// ---------------------------------------------------------------------------
// Causal softmax. Dispense rows [512,1536): write fp32 P in place.
// Other rows: write half hi/lo planes up to roundup(q+1,128).
// ---------------------------------------------------------------------------
__global__ void __launch_bounds__(256) softmax_kernel(float* __restrict__ P,
    __half* __restrict__ Ph, __half* __restrict__ Pl)
{
    int q = blockIdx.x, h = blockIdx.y;
    float* row = P + ((long)h * S + q) * S;
    int len = q + 1;
    int tid = threadIdx.x;
    __shared__ float red[256];

    float v[8];
    float mx = -3.4e38f;
#pragma unroll
    for (int i = 0; i < 8; i++) {
        int k = tid + i * 256;
        v[i] = (k < len) ? row[k] : -3.4e38f;
        mx = fmaxf(mx, v[i]);
    }
    red[tid] = mx; __syncthreads();
    for (int st = 128; st > 0; st >>= 1) {
        if (tid < st) red[tid] = fmaxf(red[tid], red[tid + st]);
        __syncthreads();
    }
    mx = red[0]; __syncthreads();

    float sum = 0.0f;
#pragma unroll
    for (int i = 0; i < 8; i++) {
        int k = tid + i * 256;
        v[i] = (k < len) ? expf(v[i] - mx) : 0.0f;
        sum += v[i];
    }
    red[tid] = sum; __syncthreads();
    for (int st = 128; st > 0; st >>= 1) {
        if (tid < st) red[tid] += red[tid + st];
        __syncthreads();
    }
    float inv = 1.0f / red[0];

    if (q >= 512 && q < 1536) {
#pragma unroll
        for (int i = 0; i < 8; i++) {
            int k = tid + i * 256;
            row[k] = v[i] * inv;
        }
    } else {
        int kmax = ((q >> 7) + 1) << 7;
        long base = (long)h * S * S + (long)q * S;
#pragma unroll
        for (int i = 0; i < 8; i++) {
            int k = tid + i * 256;
            if (k < kmax) {
                __half hh, ll; split_hl(v[i] * inv, hh, ll);
                Ph[base + k] = hh; Pl[base + k] = ll;
            }
        }
    }
}

// ---------------------------------------------------------------------------
// attention_dispense for (512,1024) [z=0] and (1024,1536) [z=1]; reads fp32
// softmaxed rows, writes half hi/lo planes.
// ---------------------------------------------------------------------------
__global__ void __launch_bounds__(256) dispense_kernel(const float* __restrict__ P,
    __half* __restrict__ Ph, __half* __restrict__ Pl)
{
    const int which = blockIdx.z;
    const int start = which ? 1024 : 512;
    const int end   = start + 512;
    const int q = start + blockIdx.x;
    const int h = blockIdx.y;
    const float* row = P + ((long)h * S + q) * S;
    const float lb = 0.5f / (float)end;
    const int tid = threadIdx.x;
    __shared__ float red[256];

    float v[6];
    float s_local = 0.0f;
#pragma unroll
    for (int i = 0; i < 6; i++) {
        int k = tid + i * 256;
        float x = (k < end) ? row[k] : 0.0f;
        x = (x >= lb) ? x : 0.0f;
        if (k == 0) x *= 0.5f;
        v[i] = x;
        s_local += x;
    }
    red[tid] = s_local; __syncthreads();
    for (int st = 128; st > 0; st >>= 1) {
        if (tid < st) red[tid] += red[tid + st];
        __syncthreads();
    }
    float elim = 1.0f - red[0];
    __syncthreads();

    if (which == 1) {
        float pm[6]; float nzl = 0.0f;
#pragma unroll
        for (int i = 0; i < 6; i++) {
            int k = tid + i * 256;
            if (k < 1024) { pm[i] = (v[i] >= lb) ? 1.0f : 0.01f; nzl += pm[i]; }
            else pm[i] = 0.0f;
        }
        red[tid] = nzl; __syncthreads();
        for (int st = 128; st > 0; st >>= 1) {
            if (tid < st) red[tid] += red[tid + st];
            __syncthreads();
        }
        float add = elim / red[0] * 0.1f;
#pragma unroll
        for (int i = 0; i < 6; i++) {
            int k = tid + i * 256;
            if (k < 512)       v[i] += 3.0f * add * pm[i];
            else if (k < 1024) v[i] += 7.0f * add * pm[i];
        }
    } else {
        float pm[6]; float nzl = 0.0f;
#pragma unroll
        for (int i = 0; i < 6; i++) {
            int k = tid + i * 256;
            if (k < 512) { pm[i] = (v[i] >= lb) ? 1.0f : 0.001f; nzl += pm[i]; }
            else pm[i] = 0.0f;
        }
        red[tid] = nzl; __syncthreads();
        for (int st = 128; st > 0; st >>= 1) {
            if (tid < st) red[tid] += red[tid + st];
            __syncthreads();
        }
        float add = elim / red[0] * 0.1f;
#pragma unroll
        for (int i = 0; i < 6; i++) {
            int k = tid + i * 256;
            if (k < 512) v[i] += 10.0f * add * pm[i];
        }
    }

    long base = (long)h * S * S + (long)q * S;
#pragma unroll
    for (int i = 0; i < 6; i++) {
        int k = tid + i * 256;
        if (k < end) {
            __half hh, ll; split_hl(v[i], hh, ll);
            Ph[base + k] = hh; Pl[base + k] = ll;
        }
    }
}

// ---------------------------------------------------------------------------
extern "C" void kernel_launch(void* const* d_in, const int* in_sizes, int n_in,
                              void* d_out, int out_size)
{
    (void)in_sizes; (void)n_in; (void)out_size;
    const float* hidden = (const float*)d_in[0];
    const int*   pos    = (const int*)d_in[2];
    const float* wq     = (const float*)d_in[3];
    const float* wk     = (const float*)d_in[4];
    const float* wv     = (const float*)d_in[5];
    const float* wo     = (const float*)d_in[6];
    float* out = (float*)d_out;

    float *pQ, *pK, *pV, *pP, *pO;
    cudaGetSymbolAddress((void**)&pQ, g_Q);
    cudaGetSymbolAddress((void**)&pK, g_K);
    cudaGetSymbolAddress((void**)&pV, g_V);
    cudaGetSymbolAddress((void**)&pP, g_P);
    cudaGetSymbolAddress((void**)&pO, g_O);
    __half *pHh, *pHl, *pWqh, *pWql, *pWkh, *pWkl, *pWvh, *pWvl, *pWoh, *pWol;
    __half *pQh, *pQl, *pKh, *pKl, *pVth, *pVtl, *pPh, *pPl, *pOh, *pOl;
    cudaGetSymbolAddress((void**)&pHh, g_Hh);   cudaGetSymbolAddress((void**)&pHl, g_Hl);
    cudaGetSymbolAddress((void**)&pWqh, g_Wqh); cudaGetSymbolAddress((void**)&pWql, g_Wql);
    cudaGetSymbolAddress((void**)&pWkh, g_Wkh); cudaGetSymbolAddress((void**)&pWkl, g_Wkl);
    cudaGetSymbolAddress((void**)&pWvh, g_Wvh); cudaGetSymbolAddress((void**)&pWvl, g_Wvl);
    cudaGetSymbolAddress((void**)&pWoh, g_Woh); cudaGetSymbolAddress((void**)&pWol, g_Wol);
    cudaGetSymbolAddress((void**)&pQh, g_Qh);   cudaGetSymbolAddress((void**)&pQl, g_Ql);
    cudaGetSymbolAddress((void**)&pKh, g_Kh);   cudaGetSymbolAddress((void**)&pKl, g_Kl);
    cudaGetSymbolAddress((void**)&pVth, g_Vth); cudaGetSymbolAddress((void**)&pVtl, g_Vtl);
    cudaGetSymbolAddress((void**)&pPh, g_Ph);   cudaGetSymbolAddress((void**)&pPl, g_Pl);
    cudaGetSymbolAddress((void**)&pOh, g_Oh);   cudaGetSymbolAddress((void**)&pOl, g_Ol);

    cudaFuncSetAttribute((const void*)hgemm_pre<0,0>, cudaFuncAttributeMaxDynamicSharedMemorySize, SMEMB);
    cudaFuncSetAttribute((const void*)hgemm_pre<1,0>, cudaFuncAttributeMaxDynamicSharedMemorySize, SMEMB);
    cudaFuncSetAttribute((const void*)hgemm_pre<0,1>, cudaFuncAttributeMaxDynamicSharedMemorySize, SMEMB);

    dim3 blk(256);
    const float scale = 0.08838834764831845f;   // 1/sqrt(128)

    // pre-split hidden + weights
    long nh4 = (long)S * HID / 4;
    long nw4 = (long)HID * HID / 4;
    convert_kernel<<<(unsigned)((nh4 + 255) / 256), 256>>>(hidden, pHh, pHl, nh4);
    convert_kernel<<<(unsigned)((nw4 + 255) / 256), 256>>>(wq, pWqh, pWql, nw4);
    convert_kernel<<<(unsigned)((nw4 + 255) / 256), 256>>>(wk, pWkh, pWkl, nw4);
    convert_kernel<<<(unsigned)((nw4 + 255) / 256), 256>>>(wv, pWvh, pWvl, nw4);
    convert_kernel<<<(unsigned)((nw4 + 255) / 256), 256>>>(wo, pWoh, pWol, nw4);

    // projections (fp32 outputs)
    dim3 gproj(HID / 128, S / 128, 1);
    hgemm_pre<0,0><<<gproj, blk, SMEMB>>>(pHh, pHl, pWqh, pWql, pQ, HID, HID, HID, HID, 0, 0, 0, 1.0f);
    hgemm_pre<0,0><<<gproj, blk, SMEMB>>>(pHh, pHl, pWkh, pWkl, pK, HID, HID, HID, HID, 0, 0, 0, 1.0f);
    hgemm_pre<0,0><<<gproj, blk, SMEMB>>>(pHh, pHl, pWvh, pWvl, pV, HID, HID, HID, HID, 0, 0, 0, 1.0f);

    // RoPE -> half planes; V -> transposed half planes
    rope_kernel<<<(S * NH * 64) / 256, 256>>>(pos, pQ, pK, pQh, pQl, pKh, pKl);
    transpv_kernel<<<dim3(S / 32, HD / 32, NH), dim3(32, 8)>>>(pV, pVth, pVtl);

    // scores (causal tile-skip), fp32 P
    dim3 gscore(S / 128, S / 128, NH);
    hgemm_pre<1,0><<<gscore, blk, SMEMB>>>(pQh, pQl, pKh, pKl, pP, HD, HID, HID, S,
                                           (long)HD, (long)HD, (long)S * S, scale);

    softmax_kernel<<<dim3(S, NH), 256>>>(pP, pPh, pPl);
    dispense_kernel<<<dim3(512, NH, 2), 256>>>(pP, pPh, pPl);

    // O_h = P_h @ Vt_h^T (NT with K-contiguous planes; KLIMIT by causality)
    dim3 gpv(1, S / 128, NH);
    hgemm_pre<0,1><<<gpv, blk, SMEMB>>>(pPh, pPl, pVth, pVtl, pO, S, S, S, HID,
                                        (long)S * S, (long)HD * S, (long)HD, 1.0f);

    // out = O @ wo^T
    convert_kernel<<<(unsigned)((nh4 + 255) / 256), 256>>>(pO, pOh, pOl, nh4);
    hgemm_pre<0,0><<<gproj, blk, SMEMB>>>(pOh, pOl, pWoh, pWol, out, HID, HID, HID, HID, 0, 0, 0, 1.0f);
}